// round 16
// baseline (speedup 1.0000x reference)
#include <cuda_runtime.h>
#include <cuda_fp16.h>
#include <stdint.h>
#include <math.h>

#define BB 64
#define TT 512
#define II 256
#define HH 1024
#define OO 10
#define KTOT 1280
#define NCOL 4096
#define GRID 128
#define NT 256

#define AROW 2560            // bytes per resident-A row (1280 k * 2B fp16)
#define OFF_B 81920          // B buffers after 80KB resident A
#define SLOT  8192           // one 64-k chunk (64 rows * 128B)
#define SLOT4 34816          // one buffer: 4 chunk slots (32KB) + scratch headroom
#define DYN_SMEM (OFF_B + 3 * SLOT4)   // 186368

#define SW(o) ((o) ^ (((o) >> 3) & 0x70))

// ---------------- persistent device state ----------------
__device__ __half g_W[NCOL * KTOT];        // [col][k], col = cta*32 + g*8 + hloc
__device__ __half g_x[BB * TT * II];
__device__ __half g_h[2][BB * HH];
__device__ unsigned int g_cnt_grp[16];
__device__ unsigned int g_cnt_top;
__device__ unsigned int g_gen;

__device__ __forceinline__ uint32_t smem_u32(const void* p) {
    uint32_t a;
    asm("{ .reg .u64 t; cvta.to.shared.u64 t, %1; cvt.u32.u64 %0, t; }" : "=r"(a) : "l"(p));
    return a;
}

#define LDSM4(r, a) \
    asm volatile("ldmatrix.sync.aligned.m8n8.x4.shared.b16 {%0,%1,%2,%3}, [%4];" \
        : "=r"((r)[0]), "=r"((r)[1]), "=r"((r)[2]), "=r"((r)[3]) : "r"(a))

#define MMA(acc, a, b0, b1) \
    asm volatile("mma.sync.aligned.m16n8k16.row.col.f32.f16.f16.f32 " \
        "{%0,%1,%2,%3},{%4,%5,%6,%7},{%8,%9},{%0,%1,%2,%3};" \
        : "+f"((acc)[0]), "+f"((acc)[1]), "+f"((acc)[2]), "+f"((acc)[3]) \
        : "r"((a)[0]), "r"((a)[1]), "r"((a)[2]), "r"((a)[3]), "r"(b0), "r"(b1))

#define CP_ASYNC(dst, src) \
    asm volatile("cp.async.cg.shared.global [%0], [%1], 16;" :: "r"(dst), "l"(src))
#define CP_COMMIT() asm volatile("cp.async.commit_group;" ::: "memory")
#define CP_WAIT0()  asm volatile("cp.async.wait_group 0;" ::: "memory")
#define CP_WAIT1()  asm volatile("cp.async.wait_group 1;" ::: "memory")

__device__ __forceinline__ unsigned atom_add_acqrel(unsigned* p, unsigned v) {
    unsigned old;
    asm volatile("atom.acq_rel.gpu.global.add.u32 %0, [%1], %2;"
                 : "=r"(old) : "l"(p), "r"(v) : "memory");
    return old;
}
__device__ __forceinline__ void st_release(unsigned* p, unsigned v) {
    asm volatile("st.release.gpu.global.u32 [%0], %1;" :: "l"(p), "r"(v) : "memory");
}
__device__ __forceinline__ unsigned ld_acquire(unsigned* p) {
    unsigned v;
    asm volatile("ld.acquire.gpu.global.u32 %0, [%1];" : "=r"(v) : "l"(p) : "memory");
    return v;
}

__device__ __forceinline__ float fast_tanh(float x) {
    float e = __expf(2.0f * x);
    return 1.0f - 2.0f / (e + 1.0f);
}
__device__ __forceinline__ float fast_sig(float x) {
    return 1.0f / (1.0f + __expf(-x));
}

// ---------------- setup ----------------
__global__ void setup_kernel(const float* __restrict__ x,
                             const float* __restrict__ Wx,
                             const float* __restrict__ Wh)
{
    int gt = blockIdx.x * blockDim.x + threadIdx.x;
    int stride = gridDim.x * blockDim.x;

    for (int i = gt; i < NCOL * KTOT; i += stride) {
        int cf = i / KTOT, k = i - cf * KTOT;
        int cta = cf >> 5, r = cf & 31;
        int g = r >> 3, hj = cta * 8 + (r & 7);
        float w = (k < HH) ? Wh[(g * HH + k) * HH + hj]
                           : Wx[(g * II + (k - HH)) * HH + hj];
        g_W[i] = __float2half(w);
    }
    for (int i = gt; i < BB * TT * II; i += stride)
        g_x[i] = __float2half(x[i]);
    for (int i = gt; i < BB * HH; i += stride)
        g_h[0][i] = __float2half(0.0f);
}

// ---------------- staging helpers (identical to R12) ----------------
__device__ __forceinline__ void stage_h(const __half* hs, int c0,
                                        uint32_t bufbase, int tid) {
#pragma unroll
    for (int s = 0; s < 8; s++) {
        int gi = tid + s * NT;
        int slot = gi >> 9;
        int rem = gi & 511;
        int n = rem >> 3, kg = rem & 7;
        int k = (c0 + slot) * 64 + kg * 8;
        const __half* src = hs + n * HH + k;
        uint32_t dst = bufbase + slot * SLOT + SW(n * 128 + kg * 16);
        CP_ASYNC(dst, src);
    }
}

__device__ __forceinline__ void stage_x(int tt, uint32_t bufbase, int tid) {
#pragma unroll
    for (int s = 0; s < 8; s++) {
        int gi = tid + s * NT;
        int slot = gi >> 9;
        int rem = gi & 511;
        int n = rem >> 3, kg = rem & 7;
        int kx = slot * 64 + kg * 8;
        const __half* src = g_x + (n * TT + tt) * II + kx;
        uint32_t dst = bufbase + slot * SLOT + SW(n * 128 + kg * 16);
        CP_ASYNC(dst, src);
    }
}

__device__ __forceinline__ void compute_chunk(uint32_t slotB, int chunk,
                                              uint32_t aB0, uint32_t aB1,
                                              uint32_t bR0,
                                              int la, int lb, int lc,
                                              float acc[2][4][4]) {
#pragma unroll
    for (int ks = 0; ks < 4; ks++) {
        uint32_t ah0[4], ah1[4], bhf[8];
        uint32_t aoff = (uint32_t)(((chunk * 8 + ks * 2 + lc) ^ la) * 16);
        LDSM4(ah0, aB0 + aoff);
        LDSM4(ah1, aB1 + aoff);
        uint32_t boff = (uint32_t)(((ks * 2 + lb) ^ la) * 16);
        LDSM4(bhf,     slotB + bR0 + boff);
        LDSM4(bhf + 4, slotB + bR0 + 2048 + boff);
        MMA(acc[0][0], ah0, bhf[0], bhf[1]);
        MMA(acc[0][1], ah0, bhf[2], bhf[3]);
        MMA(acc[0][2], ah0, bhf[4], bhf[5]);
        MMA(acc[0][3], ah0, bhf[6], bhf[7]);
        MMA(acc[1][0], ah1, bhf[0], bhf[1]);
        MMA(acc[1][1], ah1, bhf[2], bhf[3]);
        MMA(acc[1][2], ah1, bhf[4], bhf[5]);
        MMA(acc[1][3], ah1, bhf[6], bhf[7]);
    }
}

// ---------------- persistent HMMA LSTM, fp16 1-pass ----------------
__global__ __launch_bounds__(NT, 1)
void lstm_mma_kernel(const float* __restrict__ bx,
                     const float* __restrict__ bh,
                     const float* __restrict__ Wp,
                     const float* __restrict__ bp,
                     float* __restrict__ out)
{
    extern __shared__ char smem[];
    const uint32_t sb = smem_u32(smem);
    const int tid = threadIdx.x;
    const int w   = tid >> 5;
    const int l   = tid & 31;
    const int cta = blockIdx.x;
    const int col0 = cta * 32;
    const int nh = w & 1;          // batch half: rows nh*32..+31
    const int kh = w >> 1;         // k-split quarter: 0..3

    const int la = l & 7, lb = (l >> 3) & 1, lc = l >> 4;

    const unsigned base = ld_acquire(&g_gen);   // replay-safe barrier base

    const uint32_t aB0 = sb + (uint32_t)((lb * 8 + la) * AROW);
    const uint32_t aB1 = aB0 + 16 * AROW;
    const uint32_t bR0 = (uint32_t)((nh * 32 + lc * 8 + la) * 128);

    // ---- one-time: load resident A (80KB fp16) ----
#pragma unroll 4
    for (int s = 0; s < 20; s++) {
        int idx = tid + s * NT;
        int r = idx / 160, kg = idx - r * 160;
        const __half* src = g_W + (col0 + r) * KTOT + kg * 8;
        uint32_t dst = sb + r * AROW + ((kg ^ (r & 7)) * 16);
        CP_ASYNC(dst, src);
    }
    CP_COMMIT(); CP_WAIT0();
    __syncthreads();

    // epilogue ownership: thread owns b-pair (2l, 2l+1) at hjE = cta*8 + w
    const int hjE = cta * 8 + w;
    const int nh2 = l >> 4;
    const int nf2 = (l >> 2) & 3;
    const int lsrc = w * 4 + (l & 3);
    float biasE[4];
#pragma unroll
    for (int g = 0; g < 4; g++) biasE[g] = bh[g * HH + hjE] + bx[g * HH + hjE];
    float cc2[2] = {0.f, 0.f};

    // prologue: x(0) into buffer 0
    stage_x(0, sb + OFF_B, tid);
    CP_COMMIT();

    for (int t = 0; t < TT; t++) {
        const __half* hs = g_h[t & 1];
        const int bbi = (2 * t) % 3;
        const uint32_t buf0 = sb + OFF_B + (uint32_t)(((bbi + 0) % 3) * SLOT4);
        const uint32_t buf1 = sb + OFF_B + (uint32_t)(((bbi + 1) % 3) * SLOT4);
        const uint32_t buf2 = sb + OFF_B + (uint32_t)(((bbi + 2) % 3) * SLOT4);

        float acc[2][4][4];
#pragma unroll
        for (int mt = 0; mt < 2; mt++)
#pragma unroll
            for (int nf = 0; nf < 4; nf++)
#pragma unroll
                for (int e = 0; e < 4; e++) acc[mt][nf][e] = 0.f;

        // ---- iter0: compute x chunks (16..19) — overlaps other CTAs' finish ----
        CP_WAIT0();
        __syncthreads();
        compute_chunk(buf0 + kh * SLOT, 16 + kh, aB0, aB1, bR0, la, lb, lc, acc);

        // ---- grid barrier WAIT: h(t) must be fully published ----
        if (tid == 0) {
            while ((ld_acquire(&g_gen) - base) < (unsigned)t) { }
        }
        __syncthreads();

        // stage h chunks 0-3 and 4-7
        stage_h(hs, 0, buf1, tid); CP_COMMIT();
        stage_h(hs, 4, buf2, tid); CP_COMMIT();

        // ---- iter1 ----
        CP_WAIT1();
        __syncthreads();
        stage_h(hs, 8, buf0, tid); CP_COMMIT();
        compute_chunk(buf1 + kh * SLOT, 0 + kh, aB0, aB1, bR0, la, lb, lc, acc);

        // ---- iter2 ----
        CP_WAIT1();
        __syncthreads();
        stage_h(hs, 12, buf1, tid); CP_COMMIT();
        compute_chunk(buf2 + kh * SLOT, 4 + kh, aB0, aB1, bR0, la, lb, lc, acc);

        // ---- iter3 ----
        CP_WAIT1();
        __syncthreads();
        if (t + 1 < TT) { stage_x(t + 1, buf2, tid); CP_COMMIT(); }
        compute_chunk(buf0 + kh * SLOT, 8 + kh, aB0, aB1, bR0, la, lb, lc, acc);

        // ---- iter4 ----
        if (t + 1 < TT) { CP_WAIT1(); } else { CP_WAIT0(); }
        __syncthreads();
        compute_chunk(buf1 + kh * SLOT, 12 + kh, aB0, aB1, bR0, la, lb, lc, acc);

        // ---- all-warp reduction + epilogue (scratch in buf0: reads retired) ----
        // float4 layout: region(kh*2+nh)*1056 + group(mt*4+nf)*132 + l*4, e contiguous
        float* scratch = (float*)(smem + (buf0 - sb));
        {
            float4* dst = (float4*)(scratch + (kh * 2 + nh) * 1056 + l * 4);
#pragma unroll
            for (int mt = 0; mt < 2; mt++)
#pragma unroll
                for (int nf = 0; nf < 4; nf++)
                    dst[(mt * 4 + nf) * 33] =
                        make_float4(acc[mt][nf][0], acc[mt][nf][1],
                                    acc[mt][nf][2], acc[mt][nf][3]);
        }
        __syncthreads();

        {
            float z[2][4];
#pragma unroll
            for (int mt = 0; mt < 2; mt++) {
                float4 v0 = *(const float4*)(scratch + (0 + nh2) * 1056 + (mt * 4 + nf2) * 132 + lsrc * 4);
                float4 v1 = *(const float4*)(scratch + (2 + nh2) * 1056 + (mt * 4 + nf2) * 132 + lsrc * 4);
                float4 v2 = *(const float4*)(scratch + (4 + nh2) * 1056 + (mt * 4 + nf2) * 132 + lsrc * 4);
                float4 v3 = *(const float4*)(scratch + (6 + nh2) * 1056 + (mt * 4 + nf2) * 132 + lsrc * 4);
                z[mt][0] = (v0.x + v1.x) + (v2.x + v3.x);
                z[mt][1] = (v0.y + v1.y) + (v2.y + v3.y);
                z[mt][2] = (v0.z + v1.z) + (v2.z + v3.z);
                z[mt][3] = (v0.w + v1.w) + (v2.w + v3.w);
            }
            __half* hd = g_h[(t + 1) & 1];
#pragma unroll
            for (int par = 0; par < 2; par++) {
                float zg = z[0][par]     + biasE[0];
                float zi = z[0][2 + par] + biasE[1];
                float zf = z[1][par]     + biasE[2];
                float zo = z[1][2 + par] + biasE[3];
                float gg = fast_tanh(zg);
                float ii = fast_sig(zi);
                float ff = fast_sig(zf);
                float oo = fast_sig(zo);
                float cv = gg * ii + cc2[par] * ff;
                cc2[par] = cv;
                float hv = fast_tanh(cv) * oo;
                hd[(2 * l + par) * HH + hjE] = __float2half(hv);
            }
        }
        __syncthreads();   // h stores + scratch reads complete

        // ---- two-level grid barrier ARRIVE (release semantics, no full fence) ----
        if (tid == 0) {
            unsigned grp = (unsigned)cta >> 3;
            unsigned o1 = atom_add_acqrel(&g_cnt_grp[grp], 1u);
            if ((o1 & 7u) == 7u) {
                unsigned o2 = atom_add_acqrel(&g_cnt_top, 1u);
                if ((o2 & 15u) == 15u) {
                    st_release(&g_gen, base + (unsigned)(t + 1));
                }
            }
        }
    }

    // ---------- final projection + softmax (final h in buffer 0) ----------
    if (blockIdx.x < BB) {
        if (tid == 0) {
            while ((ld_acquire(&g_gen) - base) < (unsigned)TT) { }
        }
        __syncthreads();

        float* red    = (float*)(smem + OFF_B);
        float* logits = red + NT;
        const int b = blockIdx.x;
        float part[OO];
#pragma unroll
        for (int o = 0; o < OO; o++) part[o] = 0.f;
        for (int k = tid; k < HH; k += NT) {
            unsigned short uh = __ldcg((const unsigned short*)&g_h[0][b * HH + k]);
            float hv = __half2float(__ushort_as_half(uh));
#pragma unroll
            for (int o = 0; o < OO; o++) part[o] += hv * Wp[k * OO + o];
        }
        for (int o = 0; o < OO; o++) {
            red[tid] = part[o];
            __syncthreads();
            for (int s = NT / 2; s > 0; s >>= 1) {
                if (tid < s) red[tid] += red[tid + s];
                __syncthreads();
            }
            if (tid == 0) logits[o] = red[0] + bp[o];
            __syncthreads();
        }
        if (tid == 0) {
            float m = logits[0];
#pragma unroll
            for (int o = 1; o < OO; o++) m = fmaxf(m, logits[o]);
            float s = 0.f, e[OO];
#pragma unroll
            for (int o = 0; o < OO; o++) { e[o] = expf(logits[o] - m); s += e[o]; }
            float inv = 1.0f / s;
#pragma unroll
            for (int o = 0; o < OO; o++) out[b * OO + o] = e[o] * inv;
        }
    }
}

extern "C" void kernel_launch(void* const* d_in, const int* in_sizes, int n_in,
                              void* d_out, int out_size) {
    const float* x  = (const float*)d_in[0];
    const float* Wx = (const float*)d_in[1];
    const float* bx = (const float*)d_in[2];
    const float* Wh = (const float*)d_in[3];
    const float* bh = (const float*)d_in[4];
    const float* Wp = (const float*)d_in[5];
    const float* bp = (const float*)d_in[6];
    float* out = (float*)d_out;

    cudaFuncSetAttribute(lstm_mma_kernel, cudaFuncAttributeMaxDynamicSharedMemorySize, DYN_SMEM);
    setup_kernel<<<512, 256>>>(x, Wx, Wh);
    lstm_mma_kernel<<<GRID, NT, DYN_SMEM>>>(bx, bh, Wp, bp, out);
}

// round 17
// speedup vs baseline: 1.1747x; 1.1747x over previous
#include <cuda_runtime.h>
#include <cuda_fp16.h>
#include <stdint.h>
#include <math.h>

#define BB 64
#define TT 512
#define II 256
#define HH 1024
#define OO 10
#define KTOT 1280
#define NCOL 4096
#define GRID 256
#define NT 128

#define AROW 2560            // bytes per resident-A row (1280 k * 2B fp16)
#define OFF_B 81920          // B superbufs after 80KB resident A
#define SLOT  4096           // one 64-k chunk for 32 batch rows
#define SBUF  16384          // 4 slots
#define DYN_SMEM (OFF_B + 2 * SBUF)   // 114688 -> 2 CTAs/SM

#define SW(o) ((o) ^ (((o) >> 3) & 0x70))

// ---------------- persistent device state ----------------
__device__ __half g_W[NCOL * KTOT];          // [col][k], col = colgrp*32 + g*8 + hloc
__device__ __half g_x[BB * TT * II];
__device__ __half g_h2[2][2][32 * HH];       // [group][parity][b_local*HH + hj]
__device__ unsigned int g_cnt_sub[2][8];
__device__ unsigned int g_cnt_top[2];
__device__ volatile unsigned int g_gen2[2];

__device__ __forceinline__ uint32_t smem_u32(const void* p) {
    uint32_t a;
    asm("{ .reg .u64 t; cvta.to.shared.u64 t, %1; cvt.u32.u64 %0, t; }" : "=r"(a) : "l"(p));
    return a;
}

#define LDSM4(r, a) \
    asm volatile("ldmatrix.sync.aligned.m8n8.x4.shared.b16 {%0,%1,%2,%3}, [%4];" \
        : "=r"((r)[0]), "=r"((r)[1]), "=r"((r)[2]), "=r"((r)[3]) : "r"(a))

#define MMA(acc, a, b0, b1) \
    asm volatile("mma.sync.aligned.m16n8k16.row.col.f32.f16.f16.f32 " \
        "{%0,%1,%2,%3},{%4,%5,%6,%7},{%8,%9},{%0,%1,%2,%3};" \
        : "+f"((acc)[0]), "+f"((acc)[1]), "+f"((acc)[2]), "+f"((acc)[3]) \
        : "r"((a)[0]), "r"((a)[1]), "r"((a)[2]), "r"((a)[3]), "r"(b0), "r"(b1))

#define CP_ASYNC(dst, src) \
    asm volatile("cp.async.cg.shared.global [%0], [%1], 16;" :: "r"(dst), "l"(src))
#define CP_COMMIT() asm volatile("cp.async.commit_group;" ::: "memory")
#define CP_WAIT0()  asm volatile("cp.async.wait_group 0;" ::: "memory")
#define CP_WAIT1()  asm volatile("cp.async.wait_group 1;" ::: "memory")

__device__ __forceinline__ float fast_tanh(float x) {
    float e = __expf(2.0f * x);
    return 1.0f - 2.0f / (e + 1.0f);
}
__device__ __forceinline__ float fast_sig(float x) {
    return 1.0f / (1.0f + __expf(-x));
}

// ---------------- setup ----------------
__global__ void setup_kernel(const float* __restrict__ x,
                             const float* __restrict__ Wx,
                             const float* __restrict__ Wh)
{
    int gt = blockIdx.x * blockDim.x + threadIdx.x;
    int stride = gridDim.x * blockDim.x;

    for (int i = gt; i < NCOL * KTOT; i += stride) {
        int cf = i / KTOT, k = i - cf * KTOT;
        int cg = cf >> 5, r = cf & 31;
        int g = r >> 3, hj = cg * 8 + (r & 7);
        float w = (k < HH) ? Wh[(g * HH + k) * HH + hj]
                           : Wx[(g * II + (k - HH)) * HH + hj];
        g_W[i] = __float2half(w);
    }
    for (int i = gt; i < BB * TT * II; i += stride)
        g_x[i] = __float2half(x[i]);
    for (int i = gt; i < 2 * 2 * 32 * HH; i += stride)
        ((__half*)g_h2)[i] = __float2half(0.0f);
}

// ---------------- staging (32 batch rows, 4 slots per buffer) ----------------
__device__ __forceinline__ void stage_h(const __half* hs, int c0,
                                        uint32_t bufbase, int tid) {
#pragma unroll
    for (int s = 0; s < 8; s++) {
        int gi = tid + s * NT;
        int slot = gi >> 8;
        int rem = gi & 255;
        int n = rem >> 3, kg = rem & 7;
        const __half* src = hs + n * HH + (c0 + slot) * 64 + kg * 8;
        uint32_t dst = bufbase + slot * SLOT + SW(n * 128 + kg * 16);
        CP_ASYNC(dst, src);
    }
}

__device__ __forceinline__ void stage_x(int b0, int tt, uint32_t bufbase, int tid) {
#pragma unroll
    for (int s = 0; s < 8; s++) {
        int gi = tid + s * NT;
        int slot = gi >> 8;
        int rem = gi & 255;
        int n = rem >> 3, kg = rem & 7;
        const __half* src = g_x + ((b0 + n) * TT + tt) * II + slot * 64 + kg * 8;
        uint32_t dst = bufbase + slot * SLOT + SW(n * 128 + kg * 16);
        CP_ASYNC(dst, src);
    }
}

__device__ __forceinline__ void compute_chunk(uint32_t slotB, int chunk,
                                              uint32_t aB0, uint32_t aB1,
                                              uint32_t bR0,
                                              int la, int lb, int lc,
                                              float acc[2][4][4]) {
#pragma unroll
    for (int ks = 0; ks < 4; ks++) {
        uint32_t ah0[4], ah1[4], bhf[8];
        uint32_t aoff = (uint32_t)(((chunk * 8 + ks * 2 + lc) ^ la) * 16);
        LDSM4(ah0, aB0 + aoff);
        LDSM4(ah1, aB1 + aoff);
        uint32_t boff = (uint32_t)(((ks * 2 + lb) ^ la) * 16);
        LDSM4(bhf,     slotB + bR0 + boff);
        LDSM4(bhf + 4, slotB + bR0 + 2048 + boff);
        MMA(acc[0][0], ah0, bhf[0], bhf[1]);
        MMA(acc[0][1], ah0, bhf[2], bhf[3]);
        MMA(acc[0][2], ah0, bhf[4], bhf[5]);
        MMA(acc[0][3], ah0, bhf[6], bhf[7]);
        MMA(acc[1][0], ah1, bhf[0], bhf[1]);
        MMA(acc[1][1], ah1, bhf[2], bhf[3]);
        MMA(acc[1][2], ah1, bhf[4], bhf[5]);
        MMA(acc[1][3], ah1, bhf[6], bhf[7]);
    }
}

// ---------------- persistent HMMA LSTM: 2 batch chains, 2 CTAs/SM ----------------
__global__ __launch_bounds__(NT, 2)
void lstm_mma_kernel(const float* __restrict__ bx,
                     const float* __restrict__ bh,
                     const float* __restrict__ Wp,
                     const float* __restrict__ bp,
                     float* __restrict__ out)
{
    extern __shared__ char smem[];
    const uint32_t sb = smem_u32(smem);
    const int tid = threadIdx.x;
    const int w   = tid >> 5;
    const int l   = tid & 31;
    const int cta = blockIdx.x;
    const int grp = cta >> 7;           // batch chain 0/1
    const int colgrp = cta & 127;
    const int col0 = colgrp * 32;
    const int b0g = grp * 32;
    const int kh = w;                   // 4-way k-split (w = 0..3)

    const int la = l & 7, lb = (l >> 3) & 1, lc = l >> 4;

    // replay-safe bases for BOTH chains (captured before any release this launch)
    const unsigned base0 = g_gen2[0];
    const unsigned base1 = g_gen2[1];
    const unsigned baseg = grp ? base1 : base0;

    const uint32_t aB0 = sb + (uint32_t)((lb * 8 + la) * AROW);
    const uint32_t aB1 = aB0 + 16 * AROW;
    const uint32_t bR0 = (uint32_t)((lc * 8 + la) * 128);

    // ---- one-time: load resident A (80KB fp16) ----
#pragma unroll 4
    for (int s = 0; s < 40; s++) {
        int idx = tid + s * NT;
        int r = idx / 160, kg = idx - r * 160;
        const __half* src = g_W + (col0 + r) * KTOT + kg * 8;
        uint32_t dst = sb + r * AROW + ((kg ^ (r & 7)) * 16);
        CP_ASYNC(dst, src);
    }
    CP_COMMIT(); CP_WAIT0();
    __syncthreads();

    // epilogue ownership: thread owns b-pair (2*(l&15)+par) at hjE = 2w + (l>>4)
    const int hjEl = 2 * w + (l >> 4);
    const int hjG  = col0 / 4 + hjEl;            // = colgrp*8 + hjEl
    const int nfc  = (l & 15) >> 2;
    const int lp   = hjEl * 4 + (l & 3);
    float biasE[4];
#pragma unroll
    for (int g = 0; g < 4; g++) biasE[g] = bh[g * HH + hjG] + bx[g * HH + hjG];
    float cc2[2] = {0.f, 0.f};

    for (int t = 0; t < TT; t++) {
        const __half* hs = g_h2[grp][t & 1];
        const uint32_t buf0 = sb + OFF_B;
        const uint32_t buf1 = sb + OFF_B + SBUF;

        // prologue: x chunks 16..19 -> buf0 (overlaps barrier wait below)
        stage_x(b0g, t, buf0, tid);
        CP_COMMIT();

        // chain barrier wait: h(grp, t) published
        if (tid == 0) {
            while ((g_gen2[grp] - baseg) < (unsigned)t) { }
        }
        __syncthreads();
        __threadfence();

        // h chunks 0..3 -> buf1
        stage_h(hs, 0, buf1, tid);
        CP_COMMIT();

        float acc[2][4][4];
#pragma unroll
        for (int mt = 0; mt < 2; mt++)
#pragma unroll
            for (int nf = 0; nf < 4; nf++)
#pragma unroll
                for (int e = 0; e < 4; e++) acc[mt][nf][e] = 0.f;

        for (int i = 0; i < 5; i++) {
            if (i == 4) { CP_WAIT0(); } else { CP_WAIT1(); }
            __syncthreads();

            const int chunk = (i == 0) ? (16 + kh) : ((i - 1) * 4 + kh);
            const uint32_t bufB = sb + OFF_B + (uint32_t)((i & 1) * SBUF);
            compute_chunk(bufB + kh * SLOT, chunk, aB0, aB1, bR0, la, lb, lc, acc);
            __syncthreads();

            if (i + 2 < 5) {
                stage_h(hs, (i + 1) * 4, sb + OFF_B + (uint32_t)((i & 1) * SBUF), tid);
                CP_COMMIT();
            }
        }
        __syncthreads();   // all warps done reading both bufs before scratch reuse

        // ---- 4-way kh reduction + epilogue (scratch overlays drained bufs) ----
        float* scratch = (float*)(smem + OFF_B);
        {
            float* dst = scratch + kh * 1056;
#pragma unroll
            for (int mt = 0; mt < 2; mt++)
#pragma unroll
                for (int nf = 0; nf < 4; nf++)
#pragma unroll
                    for (int e = 0; e < 4; e++)
                        dst[((mt * 4 + nf) * 4 + e) * 33 + l] = acc[mt][nf][e];
        }
        __syncthreads();

        {
            float z[2][4];
#pragma unroll
            for (int mt = 0; mt < 2; mt++)
#pragma unroll
                for (int e = 0; e < 4; e++) {
                    int row = ((mt * 4 + nfc) * 4 + e) * 33 + lp;
                    float s0 = scratch[0 * 1056 + row];
                    float s1 = scratch[1 * 1056 + row];
                    float s2 = scratch[2 * 1056 + row];
                    float s3 = scratch[3 * 1056 + row];
                    z[mt][e] = (s0 + s1) + (s2 + s3);
                }
            __half* hd = g_h2[grp][(t + 1) & 1];
#pragma unroll
            for (int par = 0; par < 2; par++) {
                float zg = z[0][par]     + biasE[0];
                float zi = z[0][2 + par] + biasE[1];
                float zf = z[1][par]     + biasE[2];
                float zo = z[1][2 + par] + biasE[3];
                float gg = fast_tanh(zg);
                float ii = fast_sig(zi);
                float ff = fast_sig(zf);
                float oo = fast_sig(zo);
                float cv = gg * ii + cc2[par] * ff;
                cc2[par] = cv;
                float hv = fast_tanh(cv) * oo;
                int bl = 2 * (l & 15) + par;
                hd[bl * HH + hjG] = __float2half(hv);
            }
        }
        __syncthreads();

        // ---- per-chain two-level arrive (16-way sub, 8-way top) ----
        if (tid == 0) {
            __threadfence();
            unsigned sg = (unsigned)colgrp >> 4;
            unsigned o1 = atomicAdd(&g_cnt_sub[grp][sg], 1u);
            if ((o1 & 15u) == 15u) {
                unsigned o2 = atomicAdd(&g_cnt_top[grp], 1u);
                if ((o2 & 7u) == 7u) {
                    __threadfence();
                    g_gen2[grp] = baseg + (unsigned)(t + 1);
                }
            }
        }
    }

    // ---------- final projection + softmax ----------
    if (blockIdx.x < BB) {
        const int b = blockIdx.x;
        const int bg = b >> 5, br = b & 31;
        const unsigned bb = bg ? base1 : base0;
        if (tid == 0) {
            while ((g_gen2[bg] - bb) < (unsigned)TT) { }
        }
        __syncthreads();
        __threadfence();

        float* red    = (float*)(smem + OFF_B);
        float* logits = red + NT;
        float part[OO];
#pragma unroll
        for (int o = 0; o < OO; o++) part[o] = 0.f;
        for (int k = tid; k < HH; k += NT) {
            unsigned short uh = __ldcg((const unsigned short*)&g_h2[bg][0][br * HH + k]);
            float hv = __half2float(__ushort_as_half(uh));
#pragma unroll
            for (int o = 0; o < OO; o++) part[o] += hv * Wp[k * OO + o];
        }
        for (int o = 0; o < OO; o++) {
            red[tid] = part[o];
            __syncthreads();
            for (int s = NT / 2; s > 0; s >>= 1) {
                if (tid < s) red[tid] += red[tid + s];
                __syncthreads();
            }
            if (tid == 0) logits[o] = red[0] + bp[o];
            __syncthreads();
        }
        if (tid == 0) {
            float m = logits[0];
#pragma unroll
            for (int o = 1; o < OO; o++) m = fmaxf(m, logits[o]);
            float s = 0.f, e[OO];
#pragma unroll
            for (int o = 0; o < OO; o++) { e[o] = expf(logits[o] - m); s += e[o]; }
            float inv = 1.0f / s;
#pragma unroll
            for (int o = 0; o < OO; o++) out[b * OO + o] = e[o] * inv;
        }
    }
}

extern "C" void kernel_launch(void* const* d_in, const int* in_sizes, int n_in,
                              void* d_out, int out_size) {
    const float* x  = (const float*)d_in[0];
    const float* Wx = (const float*)d_in[1];
    const float* bx = (const float*)d_in[2];
    const float* Wh = (const float*)d_in[3];
    const float* bh = (const float*)d_in[4];
    const float* Wp = (const float*)d_in[5];
    const float* bp = (const float*)d_in[6];
    float* out = (float*)d_out;

    cudaFuncSetAttribute(lstm_mma_kernel, cudaFuncAttributeMaxDynamicSharedMemorySize, DYN_SMEM);
    setup_kernel<<<512, 256>>>(x, Wx, Wh);
    lstm_mma_kernel<<<GRID, NT, DYN_SMEM>>>(bx, bh, Wp, bp, out);
}